// round 8
// baseline (speedup 1.0000x reference)
#include <cuda_runtime.h>
#include <cuda_bf16.h>
#include <cstdint>

typedef unsigned long long u64;

// Problem constants
#define B_   16          // batch
#define N_   1152        // primary caps
#define DP   8           // dim primary
#define M_   10          // digit caps
#define DD   16          // dim digit
#define CH   8           // n per chunk (small CTA -> high residency)
#define NC   (N_ / CH)   // 144 chunks
#define SSTR 132         // float stride per nn row
#define RP   260         // float stride for transpose tile rows
#define BD   (B_ * DD)   // 256 outputs per (m)

// Partials [m][chunk][b*16+d]; counter zero-init, inc wraps -> self-reset each launch
__device__ float    g_partial[M_ * NC * BD];
__device__ unsigned g_ctr[M_];

__device__ __forceinline__ void fma2(u64& acc, u64 a, u64 b) {
    asm("fma.rn.f32x2 %0, %1, %2, %0;" : "+l"(acc) : "l"(a), "l"(b));
}
__device__ __forceinline__ void cp16(uint32_t s, const void* g) {
    asm volatile("cp.async.cg.shared.global [%0], [%1], 16;" :: "r"(s), "l"(g));
}
__device__ __forceinline__ uint32_t s2u(const void* p) {
    uint32_t a;
    asm("{ .reg .u64 t; cvta.to.shared.u64 t, %1; cvt.u32.u64 %0, t; }" : "=r"(a) : "l"(p));
    return a;
}

__global__ __launch_bounds__(128) void digitcaps_fused(
    const float* __restrict__ u,   // [B, N, DP]
    const float* __restrict__ W,   // [M, N, DD, DP]
    const float* __restrict__ Bp,  // [M, 1, N]
    float* __restrict__ out)       // [B, M, DD]
{
    __shared__ __align__(16) float smem_raw[2 * CH * SSTR];  // 8448 B; overlay 8*260*4 = 8320 B
    __shared__ float sBp[CH];
    __shared__ unsigned sLast;

    float* sW = smem_raw;             // [nn][d*8+p]
    float* sU = sW + CH * SSTR;       // [nn][b*8+p]
    float* sP = smem_raw;             // overlay after compute: [nn][RP]

    const int chunk = blockIdx.x;     // 0..143
    const int m     = blockIdx.y;     // 0..9
    const int tid   = threadIdx.x;    // 0..127
    const int n0    = chunk * CH;

    if (tid < CH) sBp[tid] = 1.0f + __ldg(&Bp[m * N_ + n0 + tid]);

    // ---- async stage W: 8 nn * 128 floats = 256 x 16B chunks (2/thread)
    {
        const float* gw = W + ((size_t)m * N_ + n0) * (DD * DP);
        #pragma unroll
        for (int r = 0; r < 2; ++r) {
            const int f  = tid + r * 128;   // 0..255
            const int nn = f >> 5;          // 32 chunks per nn
            const int k4 = (f & 31) * 4;
            cp16(s2u(&sW[nn * SSTR + k4]), gw + (size_t)nn * 128 + k4);
        }
    }
    // ---- async stage u to [nn][b*8+p]: 256 x 16B chunks (2/thread)
    {
        #pragma unroll
        for (int r = 0; r < 2; ++r) {
            const int f   = tid + r * 128;
            const int b   = f >> 4;         // 16 chunks per b
            const int rem = f & 15;
            const int nn  = rem >> 1;
            const int ph  = (rem & 1) * 4;
            cp16(s2u(&sU[nn * SSTR + b * 8 + ph]),
                 u + ((size_t)b * N_ + n0 + nn) * DP + ph);
        }
    }
    asm volatile("cp.async.commit_group;" ::: "memory");
    asm volatile("cp.async.wait_group 0;" ::: "memory");
    __syncthreads();

    // ---- compute: thread (nn_g, bg, dg) -> 4b x 4d for one nn, f32x2 over p
    const int nn_g = tid & 7;
    const int bg   = (tid >> 3) & 3;
    const int dg   = tid >> 5;

    const float sc = sBp[nn_g];
    const float* uS = &sU[nn_g * SSTR + bg * 32];
    const float* wS = &sW[nn_g * SSTR + dg * 32];

    // preload the 4 d-vectors (16 u64)
    ulonglong2 w0[4], w1[4];
    #pragma unroll
    for (int j = 0; j < 4; ++j) {
        w0[j] = *(const ulonglong2*)(wS + j * 8);
        w1[j] = *(const ulonglong2*)(wS + j * 8 + 4);
    }

    float S[4][4];
    #pragma unroll
    for (int i = 0; i < 4; ++i) {
        const ulonglong2 U0 = *(const ulonglong2*)(uS + i * 8);
        const ulonglong2 U1 = *(const ulonglong2*)(uS + i * 8 + 4);
        #pragma unroll
        for (int j = 0; j < 4; ++j) {
            u64 a = 0ull;
            fma2(a, U0.x, w0[j].x);
            fma2(a, U0.y, w0[j].y);
            fma2(a, U1.x, w1[j].x);
            fma2(a, U1.y, w1[j].y);
            const float lo = __uint_as_float((unsigned)(a & 0xffffffffu));
            const float hi = __uint_as_float((unsigned)(a >> 32));
            S[i][j] = sc * (lo + hi);
        }
    }

    // ---- smem transpose reduce over the 8 nn rows
    __syncthreads();
    {
        float* row = &sP[nn_g * RP];
        #pragma unroll
        for (int i = 0; i < 4; ++i) {
            const int bd = (bg * 4 + i) * DD + dg * 4;
            *(float4*)(row + bd) = make_float4(S[i][0], S[i][1], S[i][2], S[i][3]);
        }
    }
    __syncthreads();

    // 256 bd positions, 128 threads -> 2 each
    #pragma unroll
    for (int r = 0; r < 2; ++r) {
        const int bd = tid + r * 128;
        float Sp = sP[bd];
        #pragma unroll
        for (int nn = 1; nn < CH; ++nn) Sp += sP[nn * RP + bd];
        g_partial[((size_t)m * NC + chunk) * BD + bd] = Sp;
    }

    // ---- last CTA per m: acq_rel ordered counter
    __syncthreads();
    if (tid == 0) {
        unsigned old;
        asm volatile("atom.acq_rel.gpu.global.inc.u32 %0, [%1], %2;"
                     : "=r"(old) : "l"(&g_ctr[m]), "r"((unsigned)(NC - 1)) : "memory");
        sLast = old;
    }
    __syncthreads();
    if (sLast != NC - 1) return;

    const float* pm = &g_partial[(size_t)m * NC * BD];
    #pragma unroll
    for (int r = 0; r < 2; ++r) {
        const int bd = tid + r * 128;
        float Sv = 0.f;
        for (int c = 0; c < NC; ++c)
            Sv += __ldcg(pm + (size_t)c * BD + bd);

        float n2 = Sv * Sv;
        #pragma unroll
        for (int off = 8; off >= 1; off >>= 1)
            n2 += __shfl_xor_sync(0xFFFFFFFFu, n2, off, 16);

        const float norm  = sqrtf(n2);
        const float coef  = 1.0f - expf(-norm);
        const float scale = coef / (norm + 1e-7f);

        const int b = bd >> 4;
        const int d = bd & 15;
        out[((size_t)b * M_ + m) * DD + d] = Sv * scale;
    }
}

extern "C" void kernel_launch(void* const* d_in, const int* in_sizes, int n_in,
                              void* d_out, int out_size)
{
    const float* u  = (const float*)d_in[0];   // primary_caps [16,1152,8]
    const float* W  = (const float*)d_in[1];   // W [10,1152,16,8]
    const float* Bp = (const float*)d_in[2];   // B_prior [10,1,1152]
    float* out = (float*)d_out;                // [16,10,16]

    dim3 grid(NC, M_);
    digitcaps_fused<<<grid, 128>>>(u, W, Bp, out);
}

// round 9
// speedup vs baseline: 1.1597x; 1.1597x over previous
#include <cuda_runtime.h>
#include <cuda_bf16.h>
#include <cstdint>

typedef unsigned long long u64;

// Problem constants
#define B_   16          // batch
#define N_   1152        // primary caps
#define DP   8           // dim primary
#define M_   10          // digit caps
#define DD   16          // dim digit
#define CH   16          // n per staged chunk
#define CPC  4           // chunks per CTA
#define NPC  (CH * CPC)  // 64 n per CTA
#define NCTA (N_ / NPC)  // 18 CTAs along n
#define SSTR 132         // float stride per nn row
#define RP   260         // float stride for transpose tile rows
#define BD   (B_ * DD)   // 256
#define BUFF (2 * CH * SSTR)   // floats per buffer (sW+sU)

// Partials [m][cta_n][bd]; counter zero-init, inc wraps -> self-reset each launch
__device__ float    g_partial[M_ * NCTA * BD];
__device__ unsigned g_ctr[M_];

__device__ __forceinline__ void fma2(u64& acc, u64 a, u64 b) {
    asm("fma.rn.f32x2 %0, %1, %2, %0;" : "+l"(acc) : "l"(a), "l"(b));
}
__device__ __forceinline__ void cp16(uint32_t s, const void* g) {
    asm volatile("cp.async.cg.shared.global [%0], [%1], 16;" :: "r"(s), "l"(g));
}
__device__ __forceinline__ uint32_t s2u(const void* p) {
    uint32_t a;
    asm("{ .reg .u64 t; cvta.to.shared.u64 t, %1; cvt.u32.u64 %0, t; }" : "=r"(a) : "l"(p));
    return a;
}

__global__ __launch_bounds__(256) void digitcaps_fused(
    const float* __restrict__ u,   // [B, N, DP]
    const float* __restrict__ W,   // [M, N, DD, DP]
    const float* __restrict__ Bp,  // [M, 1, N]
    float* __restrict__ out)       // [B, M, DD]
{
    __shared__ __align__(16) float smem_raw[2 * BUFF];  // 33792 B, two stage buffers
    __shared__ float sBp[NPC];
    __shared__ unsigned sLast;

    const int cn  = blockIdx.x;      // 0..17
    const int m   = blockIdx.y;      // 0..9
    const int tid = threadIdx.x;
    const int nb  = cn * NPC;        // first n of this CTA

    if (tid < NPC) sBp[tid] = 1.0f + __ldg(&Bp[m * N_ + nb + tid]);

    // stage chunk c into buffer buf
    auto stage = [&](int c, int buf) {
        float* sW = smem_raw + buf * BUFF;
        float* sU = sW + CH * SSTR;
        const int n0 = nb + c * CH;
        const float* gw = W + ((size_t)m * N_ + n0) * (DD * DP);
        #pragma unroll
        for (int r = 0; r < 2; ++r) {
            const int f  = tid + r * 256;   // 0..511
            const int nn = f >> 5;
            const int k4 = (f & 31) * 4;
            cp16(s2u(&sW[nn * SSTR + k4]), gw + (size_t)nn * 128 + k4);
        }
        #pragma unroll
        for (int r = 0; r < 2; ++r) {
            const int f   = tid + r * 256;
            const int b   = f >> 5;
            const int rem = f & 31;
            const int nn  = rem >> 1;
            const int ph  = (rem & 1) * 4;
            cp16(s2u(&sU[nn * SSTR + b * 8 + ph]),
                 u + ((size_t)b * N_ + n0 + nn) * DP + ph);
        }
        asm volatile("cp.async.commit_group;" ::: "memory");
    };

    const int nn_g = tid & 15;
    const int bg   = (tid >> 4) & 3;
    const int dg   = tid >> 6;

    float S[4][4];
    #pragma unroll
    for (int i = 0; i < 4; ++i)
        #pragma unroll
        for (int j = 0; j < 4; ++j) S[i][j] = 0.f;

    stage(0, 0);   // prologue

    for (int c = 0; c < CPC; ++c) {
        if (c + 1 < CPC) {
            stage(c + 1, (c + 1) & 1);
            asm volatile("cp.async.wait_group 1;" ::: "memory");
        } else {
            asm volatile("cp.async.wait_group 0;" ::: "memory");
        }
        __syncthreads();

        const float* sW = smem_raw + (c & 1) * BUFF;
        const float* sU = sW + CH * SSTR;
        const float sc  = sBp[c * CH + nn_g];
        const float* uS = &sU[nn_g * SSTR + bg * 32];
        const float* wS = &sW[nn_g * SSTR + dg * 32];

        ulonglong2 U0[4], U1[4];
        #pragma unroll
        for (int i = 0; i < 4; ++i) {
            U0[i] = *(const ulonglong2*)(uS + i * 8);
            U1[i] = *(const ulonglong2*)(uS + i * 8 + 4);
        }
        #pragma unroll
        for (int j = 0; j < 4; ++j) {
            const ulonglong2 w0 = *(const ulonglong2*)(wS + j * 8);
            const ulonglong2 w1 = *(const ulonglong2*)(wS + j * 8 + 4);
            #pragma unroll
            for (int i = 0; i < 4; ++i) {
                u64 a = 0ull;
                fma2(a, U0[i].x, w0.x);
                fma2(a, U0[i].y, w0.y);
                fma2(a, U1[i].x, w1.x);
                fma2(a, U1[i].y, w1.y);
                const float lo = __uint_as_float((unsigned)(a & 0xffffffffu));
                const float hi = __uint_as_float((unsigned)(a >> 32));
                S[i][j] = fmaf(sc, lo + hi, S[i][j]);
            }
        }
        __syncthreads();   // reads done before next stage overwrites this buffer
    }

    // ---- once-per-CTA transpose reduce over the 16 nn lanes
    float* sP = smem_raw;   // overlay buffer 0: [16][RP]
    {
        float* row = &sP[nn_g * RP];
        #pragma unroll
        for (int i = 0; i < 4; ++i) {
            const int bd = (bg * 4 + i) * DD + dg * 4;
            *(float4*)(row + bd) = make_float4(S[i][0], S[i][1], S[i][2], S[i][3]);
        }
    }
    __syncthreads();

    float Sp = sP[tid];
    #pragma unroll
    for (int nn = 1; nn < 16; ++nn) Sp += sP[nn * RP + tid];

    g_partial[((size_t)m * NCTA + cn) * BD + tid] = Sp;

    // ---- last CTA per m: acq_rel ordered counter
    __syncthreads();
    if (tid == 0) {
        unsigned old;
        asm volatile("atom.acq_rel.gpu.global.inc.u32 %0, [%1], %2;"
                     : "=r"(old) : "l"(&g_ctr[m]), "r"((unsigned)(NCTA - 1)) : "memory");
        sLast = old;
    }
    __syncthreads();
    if (sLast != NCTA - 1) return;

    const float* pm = &g_partial[(size_t)m * NCTA * BD];
    float Sv = 0.f;
    #pragma unroll
    for (int c = 0; c < NCTA; ++c)
        Sv += __ldcg(pm + (size_t)c * BD + tid);

    float n2 = Sv * Sv;
    #pragma unroll
    for (int off = 8; off >= 1; off >>= 1)
        n2 += __shfl_xor_sync(0xFFFFFFFFu, n2, off, 16);

    const float norm  = sqrtf(n2);
    const float coef  = 1.0f - expf(-norm);
    const float scale = coef / (norm + 1e-7f);

    const int b = tid >> 4;
    const int d = tid & 15;
    out[((size_t)b * M_ + m) * DD + d] = Sv * scale;
}

extern "C" void kernel_launch(void* const* d_in, const int* in_sizes, int n_in,
                              void* d_out, int out_size)
{
    const float* u  = (const float*)d_in[0];   // primary_caps [16,1152,8]
    const float* W  = (const float*)d_in[1];   // W [10,1152,16,8]
    const float* Bp = (const float*)d_in[2];   // B_prior [10,1,1152]
    float* out = (float*)d_out;                // [16,10,16]

    dim3 grid(NCTA, M_);
    digitcaps_fused<<<grid, 256>>>(u, W, Bp, out);
}

// round 10
// speedup vs baseline: 1.2654x; 1.0912x over previous
#include <cuda_runtime.h>
#include <cuda_bf16.h>
#include <cstdint>

typedef unsigned long long u64;

// Problem constants
#define B_   16          // batch
#define N_   1152        // primary caps
#define DP   8           // dim primary
#define M_   10          // digit caps
#define DD   16          // dim digit
#define SUB  16          // n per staged sub-chunk
#define NSUB 2           // sub-chunks per CTA (pipelined)
#define NPC  (SUB * NSUB)    // 32 n per CTA
#define NCTA (N_ / NPC)      // 36 CTAs along n
#define SSTR 132             // float stride per nn row
#define RP   260             // float stride for transpose tile rows
#define BD   (B_ * DD)       // 256
#define BUFF (2 * SUB * SSTR)   // floats per stage buffer (sW+sU) = 4224

// Partials [m][cta_n][bd]; counter zero-init, inc wraps -> self-reset each launch
__device__ float    g_partial[M_ * NCTA * BD];
__device__ unsigned g_ctr[M_];

__device__ __forceinline__ void fma2(u64& acc, u64 a, u64 b) {
    asm("fma.rn.f32x2 %0, %1, %2, %0;" : "+l"(acc) : "l"(a), "l"(b));
}
__device__ __forceinline__ void cp16(uint32_t s, const void* g) {
    asm volatile("cp.async.cg.shared.global [%0], [%1], 16;" :: "r"(s), "l"(g));
}
__device__ __forceinline__ uint32_t s2u(const void* p) {
    uint32_t a;
    asm("{ .reg .u64 t; cvta.to.shared.u64 t, %1; cvt.u32.u64 %0, t; }" : "=r"(a) : "l"(p));
    return a;
}

__global__ __launch_bounds__(256, 4) void digitcaps_fused(
    const float* __restrict__ u,   // [B, N, DP]
    const float* __restrict__ W,   // [M, N, DD, DP]
    const float* __restrict__ Bp,  // [M, 1, N]
    float* __restrict__ out)       // [B, M, DD]
{
    __shared__ __align__(16) float smem_raw[2 * BUFF];  // 33792 B (double buffer)
    __shared__ float sBp[NPC];
    __shared__ unsigned sLast;

    const int cn  = blockIdx.x;      // 0..35
    const int m   = blockIdx.y;      // 0..9
    const int tid = threadIdx.x;
    const int nb  = cn * NPC;

    if (tid < NPC) sBp[tid] = 1.0f + __ldg(&Bp[m * N_ + nb + tid]);

    // stage sub-chunk c into buffer c&1
    auto stage = [&](int c) {
        float* sW = smem_raw + (c & 1) * BUFF;
        float* sU = sW + SUB * SSTR;
        const int n0 = nb + c * SUB;
        const float* gw = W + ((size_t)m * N_ + n0) * (DD * DP);
        #pragma unroll
        for (int r = 0; r < 2; ++r) {
            const int f  = tid + r * 256;   // 0..511
            const int nn = f >> 5;          // 32 x 16B per nn
            const int k4 = (f & 31) * 4;
            cp16(s2u(&sW[nn * SSTR + k4]), gw + (size_t)nn * 128 + k4);
        }
        #pragma unroll
        for (int r = 0; r < 2; ++r) {
            const int f   = tid + r * 256;
            const int b   = f >> 5;
            const int rem = f & 31;
            const int nn  = rem >> 1;
            const int ph  = (rem & 1) * 4;
            cp16(s2u(&sU[nn * SSTR + b * 8 + ph]),
                 u + ((size_t)b * N_ + n0 + nn) * DP + ph);
        }
        asm volatile("cp.async.commit_group;" ::: "memory");
    };

    const int nn_g = tid & 15;
    const int bg   = (tid >> 4) & 3;
    const int dg   = tid >> 6;

    float S[4][4];
    #pragma unroll
    for (int i = 0; i < 4; ++i)
        #pragma unroll
        for (int j = 0; j < 4; ++j) S[i][j] = 0.f;

    stage(0);
    stage(1);

    #pragma unroll
    for (int c = 0; c < NSUB; ++c) {
        asm volatile("cp.async.wait_group %0;" :: "n"(NSUB - 1 - 1) : "memory");
        // note: for c=0 wait_group 1 leaves chunk1 in flight; for c=1 all groups
        if (c == NSUB - 1)
            asm volatile("cp.async.wait_group 0;" ::: "memory");
        __syncthreads();

        const float* sW = smem_raw + (c & 1) * BUFF;
        const float* sU = sW + SUB * SSTR;
        const float sc  = sBp[c * SUB + nn_g];
        const float* uS = &sU[nn_g * SSTR + bg * 32];
        const float* wS = &sW[nn_g * SSTR + dg * 32];

        // preload 4 d-vectors (16 u64 -> held briefly)
        ulonglong2 w0[4], w1[4];
        #pragma unroll
        for (int j = 0; j < 4; ++j) {
            w0[j] = *(const ulonglong2*)(wS + j * 8);
            w1[j] = *(const ulonglong2*)(wS + j * 8 + 4);
        }
        #pragma unroll
        for (int i = 0; i < 4; ++i) {
            const ulonglong2 U0 = *(const ulonglong2*)(uS + i * 8);
            const ulonglong2 U1 = *(const ulonglong2*)(uS + i * 8 + 4);
            #pragma unroll
            for (int j = 0; j < 4; ++j) {
                u64 a = 0ull;
                fma2(a, U0.x, w0[j].x);
                fma2(a, U0.y, w0[j].y);
                fma2(a, U1.x, w1[j].x);
                fma2(a, U1.y, w1[j].y);
                const float lo = __uint_as_float((unsigned)(a & 0xffffffffu));
                const float hi = __uint_as_float((unsigned)(a >> 32));
                S[i][j] = fmaf(sc, lo + hi, S[i][j]);
            }
        }
        __syncthreads();
    }

    // ---- once-per-CTA transpose reduce over the 16 nn lanes
    float* sP = smem_raw;   // overlay: [16][RP] = 16640 B
    {
        float* row = &sP[nn_g * RP];
        #pragma unroll
        for (int i = 0; i < 4; ++i) {
            const int bd = (bg * 4 + i) * DD + dg * 4;
            *(float4*)(row + bd) = make_float4(S[i][0], S[i][1], S[i][2], S[i][3]);
        }
    }
    __syncthreads();

    float Sp = sP[tid];
    #pragma unroll
    for (int nn = 1; nn < 16; ++nn) Sp += sP[nn * RP + tid];

    g_partial[((size_t)m * NCTA + cn) * BD + tid] = Sp;

    // ---- last CTA per m: acq_rel ordered counter
    __syncthreads();
    if (tid == 0) {
        unsigned old;
        asm volatile("atom.acq_rel.gpu.global.inc.u32 %0, [%1], %2;"
                     : "=r"(old) : "l"(&g_ctr[m]), "r"((unsigned)(NCTA - 1)) : "memory");
        sLast = old;
    }
    __syncthreads();
    if (sLast != NCTA - 1) return;

    const float* pm = &g_partial[(size_t)m * NCTA * BD];
    float Sv = 0.f;
    #pragma unroll
    for (int c = 0; c < NCTA; ++c)
        Sv += __ldcg(pm + (size_t)c * BD + tid);

    float n2 = Sv * Sv;
    #pragma unroll
    for (int off = 8; off >= 1; off >>= 1)
        n2 += __shfl_xor_sync(0xFFFFFFFFu, n2, off, 16);

    const float norm  = sqrtf(n2);
    const float coef  = 1.0f - expf(-norm);
    const float scale = coef / (norm + 1e-7f);

    const int b = tid >> 4;
    const int d = tid & 15;
    out[((size_t)b * M_ + m) * DD + d] = Sv * scale;
}

extern "C" void kernel_launch(void* const* d_in, const int* in_sizes, int n_in,
                              void* d_out, int out_size)
{
    const float* u  = (const float*)d_in[0];   // primary_caps [16,1152,8]
    const float* W  = (const float*)d_in[1];   // W [10,1152,16,8]
    const float* Bp = (const float*)d_in[2];   // B_prior [10,1,1152]
    float* out = (float*)d_out;                // [16,10,16]

    dim3 grid(NCTA, M_);
    digitcaps_fused<<<grid, 256>>>(u, W, Bp, out);
}

// round 11
// speedup vs baseline: 1.3801x; 1.0906x over previous
#include <cuda_runtime.h>
#include <cuda_bf16.h>
#include <cstdint>

typedef unsigned long long u64;

// Problem constants
#define B_   16          // batch
#define N_   1152        // primary caps
#define DP   8           // dim primary
#define M_   10          // digit caps
#define DD   16          // dim digit
#define SUB  16          // n per staged sub-chunk
#define NSUB 6           // sub-chunks per CTA (pipelined)
#define NPC  (SUB * NSUB)    // 96 n per CTA
#define NCTA (N_ / NPC)      // 12 CTAs along n
#define NBUF 3               // pipeline depth
#define SSTR 132             // float stride per nn row
#define RP   260             // float stride for transpose tile rows
#define BD   (B_ * DD)       // 256
#define BUFF (2 * SUB * SSTR)   // floats per stage buffer (sW+sU) = 4224

// Partials [m][cta_n][bd]; counter zero-init, inc wraps -> self-reset each launch
__device__ float    g_partial[M_ * NCTA * BD];
__device__ unsigned g_ctr[M_];

__device__ __forceinline__ void fma2(u64& acc, u64 a, u64 b) {
    asm("fma.rn.f32x2 %0, %1, %2, %0;" : "+l"(acc) : "l"(a), "l"(b));
}
__device__ __forceinline__ void cp16(uint32_t s, const void* g) {
    asm volatile("cp.async.cg.shared.global [%0], [%1], 16;" :: "r"(s), "l"(g));
}
__device__ __forceinline__ uint32_t s2u(const void* p) {
    uint32_t a;
    asm("{ .reg .u64 t; cvta.to.shared.u64 t, %1; cvt.u32.u64 %0, t; }" : "=r"(a) : "l"(p));
    return a;
}

__global__ __launch_bounds__(256) void digitcaps_fused(
    const float* __restrict__ u,   // [B, N, DP]
    const float* __restrict__ W,   // [M, N, DD, DP]
    const float* __restrict__ Bp,  // [M, 1, N]
    float* __restrict__ out)       // [B, M, DD]
{
    __shared__ __align__(16) float smem_raw[NBUF * BUFF];  // 50688 B (triple buffer)
    __shared__ float sBp[NPC];
    __shared__ unsigned sLast;

    const int cn  = blockIdx.x;      // 0..11
    const int m   = blockIdx.y;      // 0..9
    const int tid = threadIdx.x;
    const int nb  = cn * NPC;

    if (tid < NPC) sBp[tid] = 1.0f + __ldg(&Bp[m * N_ + nb + tid]);

    // stage sub-chunk c into buffer c % NBUF (one commit group per chunk)
    auto stage = [&](int c) {
        float* sW = smem_raw + (c % NBUF) * BUFF;
        float* sU = sW + SUB * SSTR;
        const int n0 = nb + c * SUB;
        const float* gw = W + ((size_t)m * N_ + n0) * (DD * DP);
        #pragma unroll
        for (int r = 0; r < 2; ++r) {
            const int f  = tid + r * 256;   // 0..511
            const int nn = f >> 5;          // 32 x 16B per nn
            const int k4 = (f & 31) * 4;
            cp16(s2u(&sW[nn * SSTR + k4]), gw + (size_t)nn * 128 + k4);
        }
        #pragma unroll
        for (int r = 0; r < 2; ++r) {
            const int f   = tid + r * 256;
            const int b   = f >> 5;
            const int rem = f & 31;
            const int nn  = rem >> 1;
            const int ph  = (rem & 1) * 4;
            cp16(s2u(&sU[nn * SSTR + b * 8 + ph]),
                 u + ((size_t)b * N_ + n0 + nn) * DP + ph);
        }
        asm volatile("cp.async.commit_group;" ::: "memory");
    };

    const int nn_g = tid & 15;
    const int bg   = (tid >> 4) & 3;
    const int dg   = tid >> 6;

    float S[4][4];
    #pragma unroll
    for (int i = 0; i < 4; ++i)
        #pragma unroll
        for (int j = 0; j < 4; ++j) S[i][j] = 0.f;

    // prologue: fill the pipeline
    stage(0); stage(1); stage(2);

    #pragma unroll
    for (int c = 0; c < NSUB; ++c) {
        // chunk c complete when pending groups <= min(2, NSUB-1-c)
        if (c < NSUB - 3)
            asm volatile("cp.async.wait_group 2;" ::: "memory");
        else if (c == NSUB - 3)
            asm volatile("cp.async.wait_group 2;" ::: "memory");
        else if (c == NSUB - 2)
            asm volatile("cp.async.wait_group 1;" ::: "memory");
        else
            asm volatile("cp.async.wait_group 0;" ::: "memory");
        __syncthreads();

        const float* sW = smem_raw + (c % NBUF) * BUFF;
        const float* sU = sW + SUB * SSTR;
        const float sc  = sBp[c * SUB + nn_g];
        const float* uS = &sU[nn_g * SSTR + bg * 32];
        const float* wS = &sW[nn_g * SSTR + dg * 32];

        ulonglong2 w0[4], w1[4];
        #pragma unroll
        for (int j = 0; j < 4; ++j) {
            w0[j] = *(const ulonglong2*)(wS + j * 8);
            w1[j] = *(const ulonglong2*)(wS + j * 8 + 4);
        }
        #pragma unroll
        for (int i = 0; i < 4; ++i) {
            const ulonglong2 U0 = *(const ulonglong2*)(uS + i * 8);
            const ulonglong2 U1 = *(const ulonglong2*)(uS + i * 8 + 4);
            #pragma unroll
            for (int j = 0; j < 4; ++j) {
                u64 a = 0ull;
                fma2(a, U0.x, w0[j].x);
                fma2(a, U0.y, w0[j].y);
                fma2(a, U1.x, w1[j].x);
                fma2(a, U1.y, w1[j].y);
                const float lo = __uint_as_float((unsigned)(a & 0xffffffffu));
                const float hi = __uint_as_float((unsigned)(a >> 32));
                S[i][j] = fmaf(sc, lo + hi, S[i][j]);
            }
        }
        __syncthreads();   // all reads of this buffer done before re-staging it

        if (c + 3 < NSUB) stage(c + 3);
    }

    // ---- once-per-CTA transpose reduce over the 16 nn lanes
    float* sP = smem_raw;   // overlay buffers 0-1: [16][RP] = 16640 B
    {
        float* row = &sP[nn_g * RP];
        #pragma unroll
        for (int i = 0; i < 4; ++i) {
            const int bd = (bg * 4 + i) * DD + dg * 4;
            *(float4*)(row + bd) = make_float4(S[i][0], S[i][1], S[i][2], S[i][3]);
        }
    }
    __syncthreads();

    float Sp = sP[tid];
    #pragma unroll
    for (int nn = 1; nn < 16; ++nn) Sp += sP[nn * RP + tid];

    g_partial[((size_t)m * NCTA + cn) * BD + tid] = Sp;

    // ---- last CTA per m: acq_rel ordered counter
    __syncthreads();
    if (tid == 0) {
        unsigned old;
        asm volatile("atom.acq_rel.gpu.global.inc.u32 %0, [%1], %2;"
                     : "=r"(old) : "l"(&g_ctr[m]), "r"((unsigned)(NCTA - 1)) : "memory");
        sLast = old;
    }
    __syncthreads();
    if (sLast != NCTA - 1) return;

    const float* pm = &g_partial[(size_t)m * NCTA * BD];
    float Sv = 0.f;
    #pragma unroll
    for (int c = 0; c < NCTA; ++c)
        Sv += __ldcg(pm + (size_t)c * BD + tid);

    float n2 = Sv * Sv;
    #pragma unroll
    for (int off = 8; off >= 1; off >>= 1)
        n2 += __shfl_xor_sync(0xFFFFFFFFu, n2, off, 16);

    const float norm  = sqrtf(n2);
    const float coef  = 1.0f - expf(-norm);
    const float scale = coef / (norm + 1e-7f);

    const int b = tid >> 4;
    const int d = tid & 15;
    out[((size_t)b * M_ + m) * DD + d] = Sv * scale;
}

extern "C" void kernel_launch(void* const* d_in, const int* in_sizes, int n_in,
                              void* d_out, int out_size)
{
    const float* u  = (const float*)d_in[0];   // primary_caps [16,1152,8]
    const float* W  = (const float*)d_in[1];   // W [10,1152,16,8]
    const float* Bp = (const float*)d_in[2];   // B_prior [10,1,1152]
    float* out = (float*)d_out;                // [16,10,16]

    dim3 grid(NCTA, M_);
    digitcaps_fused<<<grid, 256>>>(u, W, Bp, out);
}

// round 12
// speedup vs baseline: 1.4090x; 1.0209x over previous
#include <cuda_runtime.h>
#include <cuda_bf16.h>
#include <cstdint>

typedef unsigned long long u64;

// Problem constants
#define B_   16          // batch
#define N_   1152        // primary caps
#define DP   8           // dim primary
#define M_   10          // digit caps
#define DD   16          // dim digit
#define SUB  16          // n per staged sub-chunk
#define NSUB 6           // sub-chunks per CTA (ALL staged upfront)
#define NPC  (SUB * NSUB)    // 96 n per CTA
#define NCTA (N_ / NPC)      // 12 CTAs along n -> grid 120 (single wave)
#define SSTR 132             // float stride per nn row
#define RP   260             // float stride for transpose tile rows
#define BD   (B_ * DD)       // 256
#define BUFF (2 * SUB * SSTR)       // floats per chunk buffer (sW+sU) = 4224
#define SMEM_DYN (NSUB * BUFF * 4)  // 101376 bytes

// Partials [m][cta_n][bd]; counter zero-init, inc wraps -> self-reset each launch
__device__ float    g_partial[M_ * NCTA * BD];
__device__ unsigned g_ctr[M_];

__device__ __forceinline__ void fma2(u64& acc, u64 a, u64 b) {
    asm("fma.rn.f32x2 %0, %1, %2, %0;" : "+l"(acc) : "l"(a), "l"(b));
}
__device__ __forceinline__ void cp16(uint32_t s, const void* g) {
    asm volatile("cp.async.cg.shared.global [%0], [%1], 16;" :: "r"(s), "l"(g));
}
__device__ __forceinline__ uint32_t s2u(const void* p) {
    uint32_t a;
    asm("{ .reg .u64 t; cvta.to.shared.u64 t, %1; cvt.u32.u64 %0, t; }" : "=r"(a) : "l"(p));
    return a;
}
template <int P> __device__ __forceinline__ void wait_grp() {
    asm volatile("cp.async.wait_group %0;" :: "n"(P) : "memory");
}

__global__ __launch_bounds__(256) void digitcaps_fused(
    const float* __restrict__ u,   // [B, N, DP]
    const float* __restrict__ W,   // [M, N, DD, DP]
    const float* __restrict__ Bp,  // [M, 1, N]
    float* __restrict__ out)       // [B, M, DD]
{
    extern __shared__ __align__(16) float smem_raw[];   // NSUB * BUFF floats
    __shared__ float sBp[NPC];
    __shared__ unsigned sLast;

    const int cn  = blockIdx.x;      // 0..11
    const int m   = blockIdx.y;      // 0..9
    const int tid = threadIdx.x;
    const int nb  = cn * NPC;

    // ---- stage ALL 6 chunks upfront (one commit group per chunk, max MLP)
    #pragma unroll
    for (int c = 0; c < NSUB; ++c) {
        float* sW = smem_raw + c * BUFF;
        float* sU = sW + SUB * SSTR;
        const int n0 = nb + c * SUB;
        const float* gw = W + ((size_t)m * N_ + n0) * (DD * DP);
        #pragma unroll
        for (int r = 0; r < 2; ++r) {
            const int f  = tid + r * 256;   // 0..511
            const int nn = f >> 5;          // 32 x 16B per nn
            const int k4 = (f & 31) * 4;
            cp16(s2u(&sW[nn * SSTR + k4]), gw + (size_t)nn * 128 + k4);
        }
        #pragma unroll
        for (int r = 0; r < 2; ++r) {
            const int f   = tid + r * 256;
            const int b   = f >> 5;
            const int rem = f & 31;
            const int nn  = rem >> 1;
            const int ph  = (rem & 1) * 4;
            cp16(s2u(&sU[nn * SSTR + b * 8 + ph]),
                 u + ((size_t)b * N_ + n0 + nn) * DP + ph);
        }
        asm volatile("cp.async.commit_group;" ::: "memory");
    }

    if (tid < NPC) sBp[tid] = 1.0f + __ldg(&Bp[m * N_ + nb + tid]);

    const int nn_g = tid & 15;
    const int bg   = (tid >> 4) & 3;
    const int dg   = tid >> 6;

    float S[4][4];
    #pragma unroll
    for (int i = 0; i < 4; ++i)
        #pragma unroll
        for (int j = 0; j < 4; ++j) S[i][j] = 0.f;

    // ---- drain chunks in order; one bar per chunk, no buffer reuse
    #pragma unroll
    for (int c = 0; c < NSUB; ++c) {
        switch (c) {
            case 0: wait_grp<NSUB - 1>(); break;
            case 1: wait_grp<NSUB - 2>(); break;
            case 2: wait_grp<NSUB - 3>(); break;
            case 3: wait_grp<NSUB - 4>(); break;
            case 4: wait_grp<NSUB - 5>(); break;
            default: wait_grp<0>(); break;
        }
        __syncthreads();   // cross-thread visibility of this chunk

        const float* sW = smem_raw + c * BUFF;
        const float* sU = sW + SUB * SSTR;
        const float sc  = sBp[c * SUB + nn_g];
        const float* uS = &sU[nn_g * SSTR + bg * 32];
        const float* wS = &sW[nn_g * SSTR + dg * 32];

        ulonglong2 w0[4], w1[4];
        #pragma unroll
        for (int j = 0; j < 4; ++j) {
            w0[j] = *(const ulonglong2*)(wS + j * 8);
            w1[j] = *(const ulonglong2*)(wS + j * 8 + 4);
        }
        #pragma unroll
        for (int i = 0; i < 4; ++i) {
            const ulonglong2 U0 = *(const ulonglong2*)(uS + i * 8);
            const ulonglong2 U1 = *(const ulonglong2*)(uS + i * 8 + 4);
            #pragma unroll
            for (int j = 0; j < 4; ++j) {
                u64 a = 0ull;
                fma2(a, U0.x, w0[j].x);
                fma2(a, U0.y, w0[j].y);
                fma2(a, U1.x, w1[j].x);
                fma2(a, U1.y, w1[j].y);
                const float lo = __uint_as_float((unsigned)(a & 0xffffffffu));
                const float hi = __uint_as_float((unsigned)(a >> 32));
                S[i][j] = fmaf(sc, lo + hi, S[i][j]);
            }
        }
    }

    // ---- once-per-CTA transpose reduce over the 16 nn lanes
    __syncthreads();   // all warps done with chunk-0 buffer before overlay
    float* sP = smem_raw;   // overlay: [16][RP] = 16640 B
    {
        float* row = &sP[nn_g * RP];
        #pragma unroll
        for (int i = 0; i < 4; ++i) {
            const int bd = (bg * 4 + i) * DD + dg * 4;
            *(float4*)(row + bd) = make_float4(S[i][0], S[i][1], S[i][2], S[i][3]);
        }
    }
    __syncthreads();

    float Sp = sP[tid];
    #pragma unroll
    for (int nn = 1; nn < 16; ++nn) Sp += sP[nn * RP + tid];

    g_partial[((size_t)m * NCTA + cn) * BD + tid] = Sp;

    // ---- last CTA per m: acq_rel ordered counter
    __syncthreads();
    if (tid == 0) {
        unsigned old;
        asm volatile("atom.acq_rel.gpu.global.inc.u32 %0, [%1], %2;"
                     : "=r"(old) : "l"(&g_ctr[m]), "r"((unsigned)(NCTA - 1)) : "memory");
        sLast = old;
    }
    __syncthreads();
    if (sLast != NCTA - 1) return;

    const float* pm = &g_partial[(size_t)m * NCTA * BD];
    float Sv = 0.f;
    #pragma unroll
    for (int c = 0; c < NCTA; ++c)
        Sv += __ldcg(pm + (size_t)c * BD + tid);

    float n2 = Sv * Sv;
    #pragma unroll
    for (int off = 8; off >= 1; off >>= 1)
        n2 += __shfl_xor_sync(0xFFFFFFFFu, n2, off, 16);

    const float norm  = sqrtf(n2);
    const float coef  = 1.0f - expf(-norm);
    const float scale = coef / (norm + 1e-7f);

    const int b = tid >> 4;
    const int d = tid & 15;
    out[((size_t)b * M_ + m) * DD + d] = Sv * scale;
}

extern "C" void kernel_launch(void* const* d_in, const int* in_sizes, int n_in,
                              void* d_out, int out_size)
{
    const float* u  = (const float*)d_in[0];   // primary_caps [16,1152,8]
    const float* W  = (const float*)d_in[1];   // W [10,1152,16,8]
    const float* Bp = (const float*)d_in[2];   // B_prior [10,1,1152]
    float* out = (float*)d_out;                // [16,10,16]

    cudaFuncSetAttribute(digitcaps_fused,
                         cudaFuncAttributeMaxDynamicSharedMemorySize, SMEM_DYN);

    dim3 grid(NCTA, M_);
    digitcaps_fused<<<grid, 256, SMEM_DYN>>>(u, W, Bp, out);
}